// round 1
// baseline (speedup 1.0000x reference)
#include <cuda_runtime.h>
#include <cstdint>

// ROI pooling (TF1 bilinear resize semantics, align_corners=False)
// img:  (1, 1024, 1024, 128) fp32, NHWC
// rois: (1, 512, 4) fp32  = (x1, y1, w, h) integral values
// out:  (1, 512, 7, 7, 128) fp32
//
// One warp per output pixel. 4 bilinear taps are each a contiguous 128-float
// (512 B) channel vector -> lane l loads float4 at channel 4*l from each tap,
// blends, stores one float4. Fully coalesced; 4 independent LDG.128 per lane.

#define POOL 7
#define NUM_ROIS 512
#define IMG_H 1024
#define IMG_W 1024
#define CH 128

__global__ __launch_bounds__(256) void roi_pool_kernel(
    const float* __restrict__ img,
    const float* __restrict__ rois,
    float* __restrict__ out)
{
    const int warpInBlock = threadIdx.x >> 5;
    const int lane        = threadIdx.x & 31;
    const int pid = blockIdx.x * (blockDim.x >> 5) + warpInBlock; // pixel id
    if (pid >= NUM_ROIS * POOL * POOL) return;

    const int roi = pid / (POOL * POOL);
    const int pix = pid - roi * (POOL * POOL);
    const int py  = pix / POOL;
    const int px  = pix - py * POOL;

    // ROI params (integral values stored as float)
    const float4 r = *reinterpret_cast<const float4*>(rois + roi * 4);
    const int x1 = (int)r.x;
    const int y1 = (int)r.y;
    const int w  = (int)r.z;
    const int h  = (int)r.w;

    // TF1 resize: src = dst * (size / POOL), fp32 exactly like the reference
    const float sy = (float)h / 7.0f;
    const float sx = (float)w / 7.0f;
    const float srcy = (float)py * sy;
    const float srcx = (float)px * sx;

    int ylo = (int)floorf(srcy);
    ylo = min(max(ylo, 0), h - 1);
    const float fy = srcy - (float)ylo;
    const int yhi = min(ylo + 1, h - 1);

    int xlo = (int)floorf(srcx);
    xlo = min(max(xlo, 0), w - 1);
    const float fx = srcx - (float)xlo;
    const int xhi = min(xlo + 1, w - 1);

    const int yloA = min(max(y1 + ylo, 0), IMG_H - 1);
    const int yhiA = min(max(y1 + yhi, 0), IMG_H - 1);
    const int xloA = min(max(x1 + xlo, 0), IMG_W - 1);
    const int xhiA = min(max(x1 + xhi, 0), IMG_W - 1);

    // Each tap is a contiguous 128-float channel vector; lane handles 4 ch.
    const float4* p00 = reinterpret_cast<const float4*>(
        img + ((size_t)yloA * IMG_W + xloA) * CH) + lane;
    const float4* p01 = reinterpret_cast<const float4*>(
        img + ((size_t)yloA * IMG_W + xhiA) * CH) + lane;
    const float4* p10 = reinterpret_cast<const float4*>(
        img + ((size_t)yhiA * IMG_W + xloA) * CH) + lane;
    const float4* p11 = reinterpret_cast<const float4*>(
        img + ((size_t)yhiA * IMG_W + xhiA) * CH) + lane;

    const float4 v00 = __ldg(p00);
    const float4 v01 = __ldg(p01);
    const float4 v10 = __ldg(p10);
    const float4 v11 = __ldg(p11);

    const float gx = 1.0f - fx;
    const float gy = 1.0f - fy;

    float4 o;
    {
        float top, bot;
        top = v00.x * gx + v01.x * fx;
        bot = v10.x * gx + v11.x * fx;
        o.x = top * gy + bot * fy;
        top = v00.y * gx + v01.y * fx;
        bot = v10.y * gx + v11.y * fx;
        o.y = top * gy + bot * fy;
        top = v00.z * gx + v01.z * fx;
        bot = v10.z * gx + v11.z * fx;
        o.z = top * gy + bot * fy;
        top = v00.w * gx + v01.w * fx;
        bot = v10.w * gx + v11.w * fx;
        o.w = top * gy + bot * fy;
    }

    float4* dst = reinterpret_cast<float4*>(
        out + (size_t)pid * CH) + lane;
    *dst = o;
}

extern "C" void kernel_launch(void* const* d_in, const int* in_sizes, int n_in,
                              void* d_out, int out_size)
{
    const float* img  = (const float*)d_in[0];  // (1,1024,1024,128) fp32
    const float* rois = (const float*)d_in[1];  // (1,512,4) fp32
    float* out = (float*)d_out;                 // (1,512,7,7,128) fp32

    const int totalPixels = NUM_ROIS * POOL * POOL;  // 25088
    const int threads = 256;                         // 8 warps = 8 pixels/block
    const int warpsPerBlock = threads / 32;
    const int blocks = (totalPixels + warpsPerBlock - 1) / warpsPerBlock;

    roi_pool_kernel<<<blocks, threads>>>(img, rois, out);
}